// round 8
// baseline (speedup 1.0000x reference)
#include <cuda_runtime.h>
#include <math.h>
#include <cstdint>

// Problem constants
#define B_ 4
#define T_ 2048
#define C_ 1024
#define H_ 16
#define D_ 64
#define BT_ (B_ * T_)           // 8192

// Scratch
__device__ float g_q[B_ * H_ * T_ * D_];    // [B,H,T,D]  (tf32-rounded)
__device__ float g_k[B_ * H_ * T_ * D_];
__device__ float g_v[B_ * H_ * T_ * D_];
__device__ float g_att[B_ * T_ * C_];       // [B,T,H*D]  (tf32-rounded)
__device__ float g_wt[3 * C_ * C_];         // K-major qkv weights (tf32-rounded)
__device__ float g_wot[C_ * C_];            // K-major Wo (tf32-rounded)
__device__ float g_xr[BT_ * C_];            // tf32-rounded x

// ===========================================================================
// Helpers
// ===========================================================================
__device__ __forceinline__ float to_tf32(float x) {
    uint32_t r;
    asm("cvt.rna.tf32.f32 %0, %1;" : "=r"(r) : "f"(x));
    return __uint_as_float(r);
}

__device__ __forceinline__ void mma_tf32(float* c, const uint32_t* a, const uint32_t* b) {
    asm volatile(
        "mma.sync.aligned.m16n8k8.row.col.f32.tf32.tf32.f32 "
        "{%0,%1,%2,%3}, {%4,%5,%6,%7}, {%8,%9}, {%0,%1,%2,%3};\n"
        : "+f"(c[0]), "+f"(c[1]), "+f"(c[2]), "+f"(c[3])
        : "r"(a[0]), "r"(a[1]), "r"(a[2]), "r"(a[3]),
          "r"(b[0]), "r"(b[1]));
}

__device__ __forceinline__ uint32_t smem_u32(const void* p) {
    return (uint32_t)__cvta_generic_to_shared(p);
}

#define CPA16(dst, src) \
    asm volatile("cp.async.ca.shared.global [%0], [%1], 16;" :: "r"(dst), "l"(src))
#define CP_COMMIT() asm volatile("cp.async.commit_group;" ::: "memory")
#define CP_WAIT0()  asm volatile("cp.async.wait_group 0;" ::: "memory")
#define CP_WAIT1()  asm volatile("cp.async.wait_group 1;" ::: "memory")

// ===========================================================================
// Dense GEMM: 128 threads / 4 warps, warp tile 64x64, block 128x128x32.
// THREE-stage cp.async pipeline, wait_group 1 (2 copies always in flight).
// ===========================================================================
#define TROW 36
#define TILE_F (128 * TROW)
#define STAGE_F (2 * TILE_F)                 // A + B per stage (9216 floats)
#define NSTAGE 3
#define GEMM_SMEM_BYTES (NSTAGE * STAGE_F * 4)   // 110592 bytes

__device__ __forceinline__ void gemm_issue_chunk(
    const float* __restrict__ A0, const float* __restrict__ B0,
    uint32_t sb32, int kc, int stg, int pr, int pc4)
{
    const uint32_t abase = sb32 + (uint32_t)(stg * STAGE_F) * 4;
    const uint32_t bbase = abase + (uint32_t)TILE_F * 4;
    #pragma unroll
    for (int l = 0; l < 8; l++) {
        const int r = pr + l * 16;
        const uint32_t so = (uint32_t)(r * TROW + pc4 * 4) * 4;
        CPA16(abase + so, A0 + (size_t)r * C_ + kc * 32 + pc4 * 4);
        CPA16(bbase + so, B0 + (size_t)r * C_ + kc * 32 + pc4 * 4);
    }
}

__device__ __forceinline__ void gemm_mainloop_mma(
    const float* __restrict__ A0, const float* __restrict__ B0,
    float* __restrict__ smf, float c[4][8][4])
{
    const int tid  = threadIdx.x;
    const int lane = tid & 31;
    const int wid  = tid >> 5;           // 0..3
    const int wm = (wid & 1) * 64;
    const int wn = (wid >> 1) * 64;
    const int qr = lane >> 2;
    const int qc = lane & 3;
    const int pc4 = tid & 7;
    const int pr  = tid >> 3;            // 0..15

    const uint32_t sb32 = smem_u32(smf);

    #pragma unroll
    for (int mf = 0; mf < 4; mf++)
        #pragma unroll
        for (int nf = 0; nf < 8; nf++)
            #pragma unroll
            for (int r = 0; r < 4; r++) c[mf][nf][r] = 0.0f;

    // prologue: 2 stages in flight
    gemm_issue_chunk(A0, B0, sb32, 0, 0, pr, pc4);
    CP_COMMIT();
    gemm_issue_chunk(A0, B0, sb32, 1, 1, pr, pc4);
    CP_COMMIT();

    int stg = 0;
    for (int kc = 0; kc < 32; kc++) {
        CP_WAIT1();          // group kc complete; kc+1 may still be in flight
        __syncthreads();
        if (kc < 30) {
            int stg2 = stg + 2;
            if (stg2 >= NSTAGE) stg2 -= NSTAGE;
            gemm_issue_chunk(A0, B0, sb32, kc + 2, stg2, pr, pc4);
        }
        CP_COMMIT();         // empty groups at the tail keep wait-count honest

        float* sA = smf + stg * STAGE_F;
        float* sB = sA + TILE_F;

        #pragma unroll
        for (int ks = 0; ks < 4; ks++) {
            const int k0 = ks * 8;
            uint32_t a[4][4];
            #pragma unroll
            for (int mf = 0; mf < 4; mf++) {
                const float* ap = sA + (wm + mf * 16 + qr) * TROW + k0 + qc;
                a[mf][0] = __float_as_uint(ap[0]);
                a[mf][1] = __float_as_uint(ap[8 * TROW]);
                a[mf][2] = __float_as_uint(ap[4]);
                a[mf][3] = __float_as_uint(ap[8 * TROW + 4]);
            }
            uint32_t b[8][2];
            #pragma unroll
            for (int nf = 0; nf < 8; nf++) {
                const float* bp = sB + (wn + nf * 8 + qr) * TROW + k0 + qc;
                b[nf][0] = __float_as_uint(bp[0]);
                b[nf][1] = __float_as_uint(bp[4]);
            }
            #pragma unroll
            for (int mf = 0; mf < 4; mf++)
                #pragma unroll
                for (int nf = 0; nf < 8; nf++)
                    mma_tf32(c[mf][nf], a[mf], b[nf]);
        }
        stg = (stg == NSTAGE - 1) ? 0 : stg + 1;
    }
}

// ===========================================================================
// Producer-side rounding kernels
// ===========================================================================
__global__ __launch_bounds__(256) void round_x(const float* __restrict__ x)
{
    const int base = (blockIdx.x * 256 + threadIdx.x) * 4;
    float4 v = *(const float4*)(x + base);
    v.x = to_tf32(v.x); v.y = to_tf32(v.y);
    v.z = to_tf32(v.z); v.w = to_tf32(v.w);
    *(float4*)(g_xr + base) = v;
}

__global__ __launch_bounds__(256) void transpose_qkv_w(
    const float* __restrict__ Wq, const float* __restrict__ Wk,
    const float* __restrict__ Wv)
{
    __shared__ float tile[32][33];
    const int z = blockIdx.z;
    const int which = z >> 4, h = z & 15;
    const float* W = (which == 0 ? Wq : (which == 1 ? Wk : Wv)) + (size_t)h * C_ * D_;
    const int c0 = blockIdx.x * 32;
    const int d0 = blockIdx.y * 32;
    const int tx = threadIdx.x & 31, ty = threadIdx.x >> 5;

    #pragma unroll
    for (int i = 0; i < 4; i++)
        tile[ty + i * 8][tx] = W[(size_t)(c0 + ty + i * 8) * D_ + d0 + tx];
    __syncthreads();
    const int nbase = which * 1024 + h * 64 + d0;
    #pragma unroll
    for (int i = 0; i < 4; i++)
        g_wt[(size_t)(nbase + ty + i * 8) * C_ + c0 + tx] = to_tf32(tile[tx][ty + i * 8]);
}

__global__ __launch_bounds__(256) void transpose_wo(const float* __restrict__ Wo)
{
    __shared__ float tile[32][33];
    const int c0 = blockIdx.x * 32;
    const int n0 = blockIdx.y * 32;
    const int tx = threadIdx.x & 31, ty = threadIdx.x >> 5;
    #pragma unroll
    for (int i = 0; i < 4; i++)
        tile[ty + i * 8][tx] = Wo[(size_t)(c0 + ty + i * 8) * C_ + n0 + tx];
    __syncthreads();
    #pragma unroll
    for (int i = 0; i < 4; i++)
        g_wot[(size_t)(n0 + ty + i * 8) * C_ + c0 + tx] = to_tf32(tile[tx][ty + i * 8]);
}

// ===========================================================================
// Kernel 1: QKV projection.  grid (64, 24), 128 threads.
// ===========================================================================
extern __shared__ __align__(16) float dyn_smf[];

__global__ __launch_bounds__(128, 2) void qkv_tc()
{
    const int mt = blockIdx.x, nt = blockIdx.y;
    const float* A0 = g_xr + (size_t)mt * 128 * C_;
    const float* B0 = g_wt + (size_t)nt * 128 * C_;

    float c[4][8][4];
    gemm_mainloop_mma(A0, B0, dyn_smf, c);

    const int tid  = threadIdx.x;
    const int lane = tid & 31;
    const int wid  = tid >> 5;
    const int wm = (wid & 1) * 64;
    const int wn = (wid >> 1) * 64;
    const int qr = lane >> 2;
    const int qc = lane & 3;

    const int nb0 = nt * 128 + wn;
    const int which = nb0 >> 10;
    const int hh = (nb0 >> 6) & 15;
    float* outb = (which == 0 ? g_q : (which == 1 ? g_k : g_v));

    #pragma unroll
    for (int mf = 0; mf < 4; mf++) {
        #pragma unroll
        for (int half = 0; half < 2; half++) {
            const int m = mt * 128 + wm + mf * 16 + qr + half * 8;
            const int b = m >> 11, t = m & (T_ - 1);
            float* op = outb + ((size_t)(b * H_ + hh) * T_ + t) * D_;
            #pragma unroll
            for (int nf = 0; nf < 8; nf++) {
                const int d = nf * 8 + qc * 2;
                float2 v = half == 0
                    ? make_float2(to_tf32(c[mf][nf][0]), to_tf32(c[mf][nf][1]))
                    : make_float2(to_tf32(c[mf][nf][2]), to_tf32(c[mf][nf][3]));
                *(float2*)(op + d) = v;
            }
        }
    }
}

// ===========================================================================
// Kernel 3: output projection + bias.  grid (64, 8), 128 threads.
// ===========================================================================
__global__ __launch_bounds__(128, 2) void proj_tc(float* __restrict__ out,
                                                  const float* __restrict__ bo)
{
    const int mt = blockIdx.x, nt = blockIdx.y;
    const float* A0 = g_att + (size_t)mt * 128 * C_;
    const float* B0 = g_wot + (size_t)nt * 128 * C_;

    float c[4][8][4];
    gemm_mainloop_mma(A0, B0, dyn_smf, c);

    const int tid  = threadIdx.x;
    const int lane = tid & 31;
    const int wid  = tid >> 5;
    const int wm = (wid & 1) * 64;
    const int wn = (wid >> 1) * 64;
    const int qr = lane >> 2;
    const int qc = lane & 3;

    #pragma unroll
    for (int mf = 0; mf < 4; mf++) {
        #pragma unroll
        for (int half = 0; half < 2; half++) {
            const int m = mt * 128 + wm + mf * 16 + qr + half * 8;
            #pragma unroll
            for (int nf = 0; nf < 8; nf++) {
                const int n = nt * 128 + wn + nf * 8 + qc * 2;
                float2 bv = *(const float2*)(bo + n);
                float2 v = half == 0
                    ? make_float2(c[mf][nf][0] + bv.x, c[mf][nf][1] + bv.y)
                    : make_float2(c[mf][nf][2] + bv.x, c[mf][nf][3] + bv.y);
                *(float2*)(out + (size_t)m * C_ + n) = v;
            }
        }
    }
}

// ===========================================================================
// Kernel 2: tensor-core causal flash attention (unchanged — known good).
// ===========================================================================
#define PSTR 68
#define KSTR 68
#define VSTR 72
#define PS_OFF 0
#define KS_OFF (128 * PSTR)
#define KBUF   (64 * KSTR)
#define VS_OFF (KS_OFF + 2 * KBUF)
#define VBUF   (64 * VSTR)
#define ATTN_SMEM_F (VS_OFF + 2 * VBUF)
#define ATTN_SMEM_BYTES (ATTN_SMEM_F * 4)

__device__ __forceinline__ void attn_issue_kv(
    const float* __restrict__ kp, const float* __restrict__ vp,
    uint32_t sb32, int sb, int buf, int tid)
{
    const float* ksrc = kp + (size_t)(sb * 64) * D_;
    const float* vsrc = vp + (size_t)(sb * 64) * D_;
    const uint32_t kdst = sb32 + (uint32_t)(KS_OFF + buf * KBUF) * 4;
    const uint32_t vdst = sb32 + (uint32_t)(VS_OFF + buf * VBUF) * 4;
    #pragma unroll
    for (int l = 0; l < 4; l++) {
        const int idx = tid + l * 256;
        const int r = idx >> 4, c4 = idx & 15;
        CPA16(kdst + (uint32_t)(r * KSTR + c4 * 4) * 4, ksrc + r * D_ + c4 * 4);
        CPA16(vdst + (uint32_t)(r * VSTR + c4 * 4) * 4, vsrc + r * D_ + c4 * 4);
    }
}

__global__ __launch_bounds__(256, 2) void attn_mma_kernel()
{
    extern __shared__ __align__(16) float sf[];
    float* Ps = sf + PS_OFF;

    const int tid  = threadIdx.x;
    const int lane = tid & 31;
    const int w    = tid >> 5;
    const int g    = lane >> 2;
    const int t    = lane & 3;
    const int qb   = blockIdx.x;
    const int bh   = blockIdx.y;

    const float* qp = g_q + (size_t)bh * T_ * D_;
    const float* kp = g_k + (size_t)bh * T_ * D_;
    const float* vp = g_v + (size_t)bh * T_ * D_;
    const uint32_t sb32 = smem_u32(sf);

    attn_issue_kv(kp, vp, sb32, 0, 0, tid);
    CP_COMMIT();

    #pragma unroll
    for (int l = 0; l < 8; l++) {
        const int idx = tid + l * 256;
        const int r = idx >> 4, c4 = idx & 15;
        float4 v = *(const float4*)(qp + (size_t)(qb * 128 + r) * D_ + c4 * 4);
        v.x *= 0.125f; v.y *= 0.125f; v.z *= 0.125f; v.w *= 0.125f;
        *(float4*)(Ps + r * PSTR + c4 * 4) = v;
    }
    __syncthreads();

    uint32_t qf[8][4];
    #pragma unroll
    for (int ks = 0; ks < 8; ks++) {
        const float* ap = Ps + (16 * w + g) * PSTR + ks * 8 + t;
        qf[ks][0] = __float_as_uint(ap[0]);
        qf[ks][1] = __float_as_uint(ap[8 * PSTR]);
        qf[ks][2] = __float_as_uint(ap[4]);
        qf[ks][3] = __float_as_uint(ap[8 * PSTR + 4]);
    }

    float o[8][4];
    #pragma unroll
    for (int nf = 0; nf < 8; nf++)
        #pragma unroll
        for (int r = 0; r < 4; r++) o[nf][r] = 0.0f;

    float mA = -1e30f, mB = -1e30f, lA = 0.0f, lB = 0.0f;
    const int rowA = qb * 128 + 16 * w + g;

    const int sbmax = qb * 2 + 1;
    for (int sb = 0; sb <= sbmax; sb++) {
        const int buf = sb & 1;
        CP_WAIT0();
        __syncthreads();
        if (sb < sbmax) {
            attn_issue_kv(kp, vp, sb32, sb + 1, buf ^ 1, tid);
            CP_COMMIT();
        }
        float* Ks = sf + KS_OFF + buf * KBUF;
        float* Vs = sf + VS_OFF + buf * VBUF;

        float s[8][4];
        #pragma unroll
        for (int nf = 0; nf < 8; nf++)
            #pragma unroll
            for (int r = 0; r < 4; r++) s[nf][r] = 0.0f;

        #pragma unroll
        for (int ks = 0; ks < 8; ks++) {
            const int k0 = ks * 8;
            #pragma unroll
            for (int nf = 0; nf < 8; nf++) {
                uint32_t b[2];
                const float* bp = Ks + (nf * 8 + g) * KSTR + k0 + t;
                b[0] = __float_as_uint(bp[0]);
                b[1] = __float_as_uint(bp[4]);
                mma_tf32(s[nf], qf[ks], b);
            }
        }

        if (sb * 64 + 63 > qb * 128 + 16 * w) {
            #pragma unroll
            for (int nf = 0; nf < 8; nf++) {
                const int c0 = sb * 64 + nf * 8 + 2 * t;
                if (c0 > rowA)     s[nf][0] = -1e30f;
                if (c0 + 1 > rowA) s[nf][1] = -1e30f;
                if (c0 > rowA + 8)     s[nf][2] = -1e30f;
                if (c0 + 1 > rowA + 8) s[nf][3] = -1e30f;
            }
        }

        float mxA = -1e30f, mxB = -1e30f;
        #pragma unroll
        for (int nf = 0; nf < 8; nf++) {
            mxA = fmaxf(mxA, fmaxf(s[nf][0], s[nf][1]));
            mxB = fmaxf(mxB, fmaxf(s[nf][2], s[nf][3]));
        }
        mxA = fmaxf(mxA, __shfl_xor_sync(0xFFFFFFFF, mxA, 1));
        mxA = fmaxf(mxA, __shfl_xor_sync(0xFFFFFFFF, mxA, 2));
        mxB = fmaxf(mxB, __shfl_xor_sync(0xFFFFFFFF, mxB, 1));
        mxB = fmaxf(mxB, __shfl_xor_sync(0xFFFFFFFF, mxB, 2));

        const float mnA = fmaxf(mA, mxA);
        const float mnB = fmaxf(mB, mxB);
        const float aA = __expf(mA - mnA);
        const float aB = __expf(mB - mnB);
        mA = mnA; mB = mnB;

        float suA = 0.0f, suB = 0.0f;
        #pragma unroll
        for (int nf = 0; nf < 8; nf++) {
            float p0 = __expf(s[nf][0] - mnA);
            float p1 = __expf(s[nf][1] - mnA);
            float p2 = __expf(s[nf][2] - mnB);
            float p3 = __expf(s[nf][3] - mnB);
            suA += p0 + p1; suB += p2 + p3;
            s[nf][0] = to_tf32(p0); s[nf][1] = to_tf32(p1);
            s[nf][2] = to_tf32(p2); s[nf][3] = to_tf32(p3);
        }
        suA += __shfl_xor_sync(0xFFFFFFFF, suA, 1);
        suA += __shfl_xor_sync(0xFFFFFFFF, suA, 2);
        suB += __shfl_xor_sync(0xFFFFFFFF, suB, 1);
        suB += __shfl_xor_sync(0xFFFFFFFF, suB, 2);
        lA = lA * aA + suA;
        lB = lB * aB + suB;

        #pragma unroll
        for (int nf = 0; nf < 8; nf++) {
            o[nf][0] *= aA; o[nf][1] *= aA;
            o[nf][2] *= aB; o[nf][3] *= aB;
        }

        #pragma unroll
        for (int nf = 0; nf < 8; nf++) {
            *(float2*)(Ps + (16 * w + g) * PSTR + nf * 8 + 2 * t) =
                make_float2(s[nf][0], s[nf][1]);
            *(float2*)(Ps + (16 * w + g + 8) * PSTR + nf * 8 + 2 * t) =
                make_float2(s[nf][2], s[nf][3]);
        }
        __syncwarp();

        #pragma unroll
        for (int ks = 0; ks < 8; ks++) {
            const int k0 = ks * 8;
            uint32_t a[4];
            const float* ap = Ps + (16 * w + g) * PSTR + k0 + t;
            a[0] = __float_as_uint(ap[0]);
            a[1] = __float_as_uint(ap[8 * PSTR]);
            a[2] = __float_as_uint(ap[4]);
            a[3] = __float_as_uint(ap[8 * PSTR + 4]);
            #pragma unroll
            for (int nf = 0; nf < 8; nf++) {
                uint32_t b[2];
                b[0] = __float_as_uint(Vs[(k0 + t) * VSTR + nf * 8 + g]);
                b[1] = __float_as_uint(Vs[(k0 + t + 4) * VSTR + nf * 8 + g]);
                mma_tf32(o[nf], a, b);
            }
        }
    }

    const int b = bh >> 4, h = bh & 15;
    const float invA = 1.0f / lA;
    const float invB = 1.0f / lB;
    float* dstA = g_att + ((size_t)(b * T_ + rowA)) * C_ + h * D_;
    float* dstB = g_att + ((size_t)(b * T_ + rowA + 8)) * C_ + h * D_;
    #pragma unroll
    for (int nf = 0; nf < 8; nf++) {
        const int cc = nf * 8 + 2 * t;
        *(float2*)(dstA + cc) =
            make_float2(to_tf32(o[nf][0] * invA), to_tf32(o[nf][1] * invA));
        *(float2*)(dstB + cc) =
            make_float2(to_tf32(o[nf][2] * invB), to_tf32(o[nf][3] * invB));
    }
}

// ===========================================================================
extern "C" void kernel_launch(void* const* d_in, const int* in_sizes, int n_in,
                              void* d_out, int out_size)
{
    const float* x  = (const float*)d_in[0];
    const float* Wq = (const float*)d_in[1];
    const float* Wk = (const float*)d_in[2];
    const float* Wv = (const float*)d_in[3];
    const float* Wo = (const float*)d_in[4];
    const float* bo = (const float*)d_in[5];
    float* out = (float*)d_out;

    cudaFuncSetAttribute(attn_mma_kernel, cudaFuncAttributeMaxDynamicSharedMemorySize,
                         ATTN_SMEM_BYTES);
    cudaFuncSetAttribute(qkv_tc, cudaFuncAttributeMaxDynamicSharedMemorySize,
                         GEMM_SMEM_BYTES);
    cudaFuncSetAttribute(proj_tc, cudaFuncAttributeMaxDynamicSharedMemorySize,
                         GEMM_SMEM_BYTES);

    round_x<<<BT_ * C_ / (256 * 4), 256>>>(x);
    transpose_qkv_w<<<dim3(32, 2, 48), 256>>>(Wq, Wk, Wv);
    transpose_wo<<<dim3(32, 32), 256>>>(Wo);
    qkv_tc<<<dim3(64, 24), 128, GEMM_SMEM_BYTES>>>();
    attn_mma_kernel<<<dim3(T_ / 128, B_ * H_), 256, ATTN_SMEM_BYTES>>>();
    proj_tc<<<dim3(64, 8), 128, GEMM_SMEM_BYTES>>>(out, bo);
}

// round 9
// speedup vs baseline: 1.0337x; 1.0337x over previous
#include <cuda_runtime.h>
#include <math.h>
#include <cstdint>

// Problem constants
#define B_ 4
#define T_ 2048
#define C_ 1024
#define H_ 16
#define D_ 64
#define BT_ (B_ * T_)           // 8192

// Scratch
__device__ float g_q[B_ * H_ * T_ * D_];    // [B,H,T,D]  (tf32-rounded)
__device__ float g_k[B_ * H_ * T_ * D_];
__device__ float g_v[B_ * H_ * T_ * D_];
__device__ float g_att[B_ * T_ * C_];       // [B,T,H*D]  (tf32-rounded)
__device__ float g_wt[3 * C_ * C_];         // K-major qkv weights (tf32-rounded)
__device__ float g_wot[C_ * C_];            // K-major Wo (tf32-rounded)
__device__ float g_xr[BT_ * C_];            // tf32-rounded x

// ===========================================================================
// Helpers
// ===========================================================================
__device__ __forceinline__ float to_tf32(float x) {
    uint32_t r;
    asm("cvt.rna.tf32.f32 %0, %1;" : "=r"(r) : "f"(x));
    return __uint_as_float(r);
}

__device__ __forceinline__ void mma_tf32(float* c, const uint32_t* a, const uint32_t* b) {
    asm volatile(
        "mma.sync.aligned.m16n8k8.row.col.f32.tf32.tf32.f32 "
        "{%0,%1,%2,%3}, {%4,%5,%6,%7}, {%8,%9}, {%0,%1,%2,%3};\n"
        : "+f"(c[0]), "+f"(c[1]), "+f"(c[2]), "+f"(c[3])
        : "r"(a[0]), "r"(a[1]), "r"(a[2]), "r"(a[3]),
          "r"(b[0]), "r"(b[1]));
}

__device__ __forceinline__ uint32_t smem_u32(const void* p) {
    return (uint32_t)__cvta_generic_to_shared(p);
}

#define CPA16(dst, src) \
    asm volatile("cp.async.ca.shared.global [%0], [%1], 16;" :: "r"(dst), "l"(src))
#define CP_COMMIT() asm volatile("cp.async.commit_group;" ::: "memory")
#define CP_WAIT0()  asm volatile("cp.async.wait_group 0;" ::: "memory")

// ===========================================================================
// Dense GEMM: 128 threads / 4 warps, warp tile 64x64, block 128x128x32.
// TWO-stage cp.async (R6 known-good).
// ===========================================================================
#define TROW 36
#define TILE_F (128 * TROW)
#define BUF_F  (2 * TILE_F)
#define GEMM_SMEM_BYTES (2 * BUF_F * 4)

__device__ __forceinline__ void gemm_issue_chunk(
    const float* __restrict__ A0, const float* __restrict__ B0,
    uint32_t sb32, int kc, int buf, int pr, int pc4)
{
    const uint32_t abase = sb32 + (uint32_t)(buf * BUF_F) * 4;
    const uint32_t bbase = abase + (uint32_t)TILE_F * 4;
    #pragma unroll
    for (int l = 0; l < 8; l++) {
        const int r = pr + l * 16;
        const uint32_t so = (uint32_t)(r * TROW + pc4 * 4) * 4;
        CPA16(abase + so, A0 + (size_t)r * C_ + kc * 32 + pc4 * 4);
        CPA16(bbase + so, B0 + (size_t)r * C_ + kc * 32 + pc4 * 4);
    }
}

__device__ __forceinline__ void gemm_mainloop_mma(
    const float* __restrict__ A0, const float* __restrict__ B0,
    float* __restrict__ smf, float c[4][8][4])
{
    const int tid  = threadIdx.x;
    const int lane = tid & 31;
    const int wid  = tid >> 5;
    const int wm = (wid & 1) * 64;
    const int wn = (wid >> 1) * 64;
    const int qr = lane >> 2;
    const int qc = lane & 3;
    const int pc4 = tid & 7;
    const int pr  = tid >> 3;

    const uint32_t sb32 = smem_u32(smf);

    #pragma unroll
    for (int mf = 0; mf < 4; mf++)
        #pragma unroll
        for (int nf = 0; nf < 8; nf++)
            #pragma unroll
            for (int r = 0; r < 4; r++) c[mf][nf][r] = 0.0f;

    gemm_issue_chunk(A0, B0, sb32, 0, 0, pr, pc4);
    CP_COMMIT();

    for (int kc = 0; kc < 32; kc++) {
        const int buf = kc & 1;
        CP_WAIT0();
        __syncthreads();
        if (kc < 31) {
            gemm_issue_chunk(A0, B0, sb32, kc + 1, buf ^ 1, pr, pc4);
            CP_COMMIT();
        }

        float* sA = smf + buf * BUF_F;
        float* sB = sA + TILE_F;

        #pragma unroll
        for (int ks = 0; ks < 4; ks++) {
            const int k0 = ks * 8;
            uint32_t a[4][4];
            #pragma unroll
            for (int mf = 0; mf < 4; mf++) {
                const float* ap = sA + (wm + mf * 16 + qr) * TROW + k0 + qc;
                a[mf][0] = __float_as_uint(ap[0]);
                a[mf][1] = __float_as_uint(ap[8 * TROW]);
                a[mf][2] = __float_as_uint(ap[4]);
                a[mf][3] = __float_as_uint(ap[8 * TROW + 4]);
            }
            uint32_t b[8][2];
            #pragma unroll
            for (int nf = 0; nf < 8; nf++) {
                const float* bp = sB + (wn + nf * 8 + qr) * TROW + k0 + qc;
                b[nf][0] = __float_as_uint(bp[0]);
                b[nf][1] = __float_as_uint(bp[4]);
            }
            #pragma unroll
            for (int mf = 0; mf < 4; mf++)
                #pragma unroll
                for (int nf = 0; nf < 8; nf++)
                    mma_tf32(c[mf][nf], a[mf], b[nf]);
        }
    }
}

// ===========================================================================
// Producer-side rounding kernels
// ===========================================================================
__global__ __launch_bounds__(256) void round_x(const float* __restrict__ x)
{
    const int base = (blockIdx.x * 256 + threadIdx.x) * 4;
    float4 v = *(const float4*)(x + base);
    v.x = to_tf32(v.x); v.y = to_tf32(v.y);
    v.z = to_tf32(v.z); v.w = to_tf32(v.w);
    *(float4*)(g_xr + base) = v;
}

__global__ __launch_bounds__(256) void transpose_qkv_w(
    const float* __restrict__ Wq, const float* __restrict__ Wk,
    const float* __restrict__ Wv)
{
    __shared__ float tile[32][33];
    const int z = blockIdx.z;
    const int which = z >> 4, h = z & 15;
    const float* W = (which == 0 ? Wq : (which == 1 ? Wk : Wv)) + (size_t)h * C_ * D_;
    const int c0 = blockIdx.x * 32;
    const int d0 = blockIdx.y * 32;
    const int tx = threadIdx.x & 31, ty = threadIdx.x >> 5;

    #pragma unroll
    for (int i = 0; i < 4; i++)
        tile[ty + i * 8][tx] = W[(size_t)(c0 + ty + i * 8) * D_ + d0 + tx];
    __syncthreads();
    const int nbase = which * 1024 + h * 64 + d0;
    #pragma unroll
    for (int i = 0; i < 4; i++)
        g_wt[(size_t)(nbase + ty + i * 8) * C_ + c0 + tx] = to_tf32(tile[tx][ty + i * 8]);
}

__global__ __launch_bounds__(256) void transpose_wo(const float* __restrict__ Wo)
{
    __shared__ float tile[32][33];
    const int c0 = blockIdx.x * 32;
    const int n0 = blockIdx.y * 32;
    const int tx = threadIdx.x & 31, ty = threadIdx.x >> 5;
    #pragma unroll
    for (int i = 0; i < 4; i++)
        tile[ty + i * 8][tx] = Wo[(size_t)(c0 + ty + i * 8) * C_ + n0 + tx];
    __syncthreads();
    #pragma unroll
    for (int i = 0; i < 4; i++)
        g_wot[(size_t)(n0 + ty + i * 8) * C_ + c0 + tx] = to_tf32(tile[tx][ty + i * 8]);
}

// ===========================================================================
// Kernel 1: QKV projection.  grid (64, 24), 128 threads.
// ===========================================================================
extern __shared__ __align__(16) float dyn_smf[];

__global__ __launch_bounds__(128, 2) void qkv_tc()
{
    const int mt = blockIdx.x, nt = blockIdx.y;
    const float* A0 = g_xr + (size_t)mt * 128 * C_;
    const float* B0 = g_wt + (size_t)nt * 128 * C_;

    float c[4][8][4];
    gemm_mainloop_mma(A0, B0, dyn_smf, c);

    const int tid  = threadIdx.x;
    const int lane = tid & 31;
    const int wid  = tid >> 5;
    const int wm = (wid & 1) * 64;
    const int wn = (wid >> 1) * 64;
    const int qr = lane >> 2;
    const int qc = lane & 3;

    const int nb0 = nt * 128 + wn;
    const int which = nb0 >> 10;
    const int hh = (nb0 >> 6) & 15;
    float* outb = (which == 0 ? g_q : (which == 1 ? g_k : g_v));

    #pragma unroll
    for (int mf = 0; mf < 4; mf++) {
        #pragma unroll
        for (int half = 0; half < 2; half++) {
            const int m = mt * 128 + wm + mf * 16 + qr + half * 8;
            const int b = m >> 11, t = m & (T_ - 1);
            float* op = outb + ((size_t)(b * H_ + hh) * T_ + t) * D_;
            #pragma unroll
            for (int nf = 0; nf < 8; nf++) {
                const int d = nf * 8 + qc * 2;
                float2 v = half == 0
                    ? make_float2(to_tf32(c[mf][nf][0]), to_tf32(c[mf][nf][1]))
                    : make_float2(to_tf32(c[mf][nf][2]), to_tf32(c[mf][nf][3]));
                *(float2*)(op + d) = v;
            }
        }
    }
}

// ===========================================================================
// Kernel 3: output projection + bias.  grid (64, 8), 128 threads.
// ===========================================================================
__global__ __launch_bounds__(128, 2) void proj_tc(float* __restrict__ out,
                                                  const float* __restrict__ bo)
{
    const int mt = blockIdx.x, nt = blockIdx.y;
    const float* A0 = g_att + (size_t)mt * 128 * C_;
    const float* B0 = g_wot + (size_t)nt * 128 * C_;

    float c[4][8][4];
    gemm_mainloop_mma(A0, B0, dyn_smf, c);

    const int tid  = threadIdx.x;
    const int lane = tid & 31;
    const int wid  = tid >> 5;
    const int wm = (wid & 1) * 64;
    const int wn = (wid >> 1) * 64;
    const int qr = lane >> 2;
    const int qc = lane & 3;

    #pragma unroll
    for (int mf = 0; mf < 4; mf++) {
        #pragma unroll
        for (int half = 0; half < 2; half++) {
            const int m = mt * 128 + wm + mf * 16 + qr + half * 8;
            #pragma unroll
            for (int nf = 0; nf < 8; nf++) {
                const int n = nt * 128 + wn + nf * 8 + qc * 2;
                float2 bv = *(const float2*)(bo + n);
                float2 v = half == 0
                    ? make_float2(c[mf][nf][0] + bv.x, c[mf][nf][1] + bv.y)
                    : make_float2(c[mf][nf][2] + bv.x, c[mf][nf][3] + bv.y);
                *(float2*)(out + (size_t)m * C_ + n) = v;
            }
        }
    }
}

// ===========================================================================
// Kernel 2: tensor-core causal flash attention, S-PIPELINED.
// Loop order per iteration: softmax(sb) -> PV(sb) -> wait/barrier/prefetch ->
// S(sb+1).  PV(sb)+S(sb+1) queue back-to-back in the tensor pipe while the
// next softmax's dependency chain executes.
// ===========================================================================
#define PSTR 68
#define KSTR 68
#define VSTR 72
#define PS_OFF 0
#define KS_OFF (128 * PSTR)
#define KBUF   (64 * KSTR)
#define VS_OFF (KS_OFF + 2 * KBUF)
#define VBUF   (64 * VSTR)
#define ATTN_SMEM_F (VS_OFF + 2 * VBUF)
#define ATTN_SMEM_BYTES (ATTN_SMEM_F * 4)

__device__ __forceinline__ void attn_issue_kv(
    const float* __restrict__ kp, const float* __restrict__ vp,
    uint32_t sb32, int sb, int buf, int tid)
{
    const float* ksrc = kp + (size_t)(sb * 64) * D_;
    const float* vsrc = vp + (size_t)(sb * 64) * D_;
    const uint32_t kdst = sb32 + (uint32_t)(KS_OFF + buf * KBUF) * 4;
    const uint32_t vdst = sb32 + (uint32_t)(VS_OFF + buf * VBUF) * 4;
    #pragma unroll
    for (int l = 0; l < 4; l++) {
        const int idx = tid + l * 256;
        const int r = idx >> 4, c4 = idx & 15;
        CPA16(kdst + (uint32_t)(r * KSTR + c4 * 4) * 4, ksrc + r * D_ + c4 * 4);
        CPA16(vdst + (uint32_t)(r * VSTR + c4 * 4) * 4, vsrc + r * D_ + c4 * 4);
    }
}

// S = Q @ K^T fragment MMAs for one 64-col s-block
__device__ __forceinline__ void attn_s_mma(
    float s[8][4], const uint32_t qf[8][4], const float* Ks, int g, int t)
{
    #pragma unroll
    for (int nf = 0; nf < 8; nf++)
        #pragma unroll
        for (int r = 0; r < 4; r++) s[nf][r] = 0.0f;
    #pragma unroll
    for (int ks = 0; ks < 8; ks++) {
        const int k0 = ks * 8;
        #pragma unroll
        for (int nf = 0; nf < 8; nf++) {
            uint32_t b[2];
            const float* bp = Ks + (nf * 8 + g) * KSTR + k0 + t;
            b[0] = __float_as_uint(bp[0]);
            b[1] = __float_as_uint(bp[4]);
            mma_tf32(s[nf], qf[ks], b);
        }
    }
}

__global__ __launch_bounds__(256, 2) void attn_mma_kernel()
{
    extern __shared__ __align__(16) float sf[];
    float* Ps = sf + PS_OFF;

    const int tid  = threadIdx.x;
    const int lane = tid & 31;
    const int w    = tid >> 5;
    const int g    = lane >> 2;
    const int t    = lane & 3;
    const int qb   = blockIdx.x;
    const int bh   = blockIdx.y;

    const float* qp = g_q + (size_t)bh * T_ * D_;
    const float* kp = g_k + (size_t)bh * T_ * D_;
    const float* vp = g_v + (size_t)bh * T_ * D_;
    const uint32_t sb32 = smem_u32(sf);

    attn_issue_kv(kp, vp, sb32, 0, 0, tid);
    CP_COMMIT();

    // stage Q (scaled by 0.125) into Ps
    #pragma unroll
    for (int l = 0; l < 8; l++) {
        const int idx = tid + l * 256;
        const int r = idx >> 4, c4 = idx & 15;
        float4 v = *(const float4*)(qp + (size_t)(qb * 128 + r) * D_ + c4 * 4);
        v.x *= 0.125f; v.y *= 0.125f; v.z *= 0.125f; v.w *= 0.125f;
        *(float4*)(Ps + r * PSTR + c4 * 4) = v;
    }
    __syncthreads();

    uint32_t qf[8][4];
    #pragma unroll
    for (int ks = 0; ks < 8; ks++) {
        const float* ap = Ps + (16 * w + g) * PSTR + ks * 8 + t;
        qf[ks][0] = __float_as_uint(ap[0]);
        qf[ks][1] = __float_as_uint(ap[8 * PSTR]);
        qf[ks][2] = __float_as_uint(ap[4]);
        qf[ks][3] = __float_as_uint(ap[8 * PSTR + 4]);
    }

    float o[8][4];
    #pragma unroll
    for (int nf = 0; nf < 8; nf++)
        #pragma unroll
        for (int r = 0; r < 4; r++) o[nf][r] = 0.0f;

    float mA = -1e30f, mB = -1e30f, lA = 0.0f, lB = 0.0f;
    const int rowA = qb * 128 + 16 * w + g;
    const int sbmax = qb * 2 + 1;

    // ---- prologue: K/V(0) ready, prefetch (1), compute S(0) ----
    CP_WAIT0();
    __syncthreads();
    attn_issue_kv(kp, vp, sb32, 1, 1, tid);   // sbmax >= 1 always
    CP_COMMIT();

    float s[8][4];
    attn_s_mma(s, qf, sf + KS_OFF /* buf 0 */, g, t);

    for (int sb = 0; sb <= sbmax; sb++) {
        const int buf = sb & 1;
        float* Vs = sf + VS_OFF + buf * VBUF;

        // ---- causal mask ----
        if (sb * 64 + 63 > qb * 128 + 16 * w) {
            #pragma unroll
            for (int nf = 0; nf < 8; nf++) {
                const int c0 = sb * 64 + nf * 8 + 2 * t;
                if (c0 > rowA)     s[nf][0] = -1e30f;
                if (c0 + 1 > rowA) s[nf][1] = -1e30f;
                if (c0 > rowA + 8)     s[nf][2] = -1e30f;
                if (c0 + 1 > rowA + 8) s[nf][3] = -1e30f;
            }
        }

        // ---- online softmax ----
        float mxA = -1e30f, mxB = -1e30f;
        #pragma unroll
        for (int nf = 0; nf < 8; nf++) {
            mxA = fmaxf(mxA, fmaxf(s[nf][0], s[nf][1]));
            mxB = fmaxf(mxB, fmaxf(s[nf][2], s[nf][3]));
        }
        mxA = fmaxf(mxA, __shfl_xor_sync(0xFFFFFFFF, mxA, 1));
        mxA = fmaxf(mxA, __shfl_xor_sync(0xFFFFFFFF, mxA, 2));
        mxB = fmaxf(mxB, __shfl_xor_sync(0xFFFFFFFF, mxB, 1));
        mxB = fmaxf(mxB, __shfl_xor_sync(0xFFFFFFFF, mxB, 2));

        const float mnA = fmaxf(mA, mxA);
        const float mnB = fmaxf(mB, mxB);
        const float aA = __expf(mA - mnA);
        const float aB = __expf(mB - mnB);
        mA = mnA; mB = mnB;

        float sA0 = 0.f, sA1 = 0.f, sB0 = 0.f, sB1 = 0.f;
        #pragma unroll
        for (int nf = 0; nf < 8; nf++) {
            float p0 = __expf(s[nf][0] - mnA);
            float p1 = __expf(s[nf][1] - mnA);
            float p2 = __expf(s[nf][2] - mnB);
            float p3 = __expf(s[nf][3] - mnB);
            sA0 += p0; sA1 += p1; sB0 += p2; sB1 += p3;
            s[nf][0] = to_tf32(p0); s[nf][1] = to_tf32(p1);
            s[nf][2] = to_tf32(p2); s[nf][3] = to_tf32(p3);
        }
        float suA = sA0 + sA1, suB = sB0 + sB1;
        suA += __shfl_xor_sync(0xFFFFFFFF, suA, 1);
        suA += __shfl_xor_sync(0xFFFFFFFF, suA, 2);
        suB += __shfl_xor_sync(0xFFFFFFFF, suB, 1);
        suB += __shfl_xor_sync(0xFFFFFFFF, suB, 2);
        lA = lA * aA + suA;
        lB = lB * aB + suB;

        #pragma unroll
        for (int nf = 0; nf < 8; nf++) {
            o[nf][0] *= aA; o[nf][1] *= aA;
            o[nf][2] *= aB; o[nf][3] *= aB;
        }

        // ---- P to warp-private SMEM rows ----
        #pragma unroll
        for (int nf = 0; nf < 8; nf++) {
            *(float2*)(Ps + (16 * w + g) * PSTR + nf * 8 + 2 * t) =
                make_float2(s[nf][0], s[nf][1]);
            *(float2*)(Ps + (16 * w + g + 8) * PSTR + nf * 8 + 2 * t) =
                make_float2(s[nf][2], s[nf][3]);
        }
        __syncwarp();

        // ---- O += P @ V(sb) ----
        #pragma unroll
        for (int ks = 0; ks < 8; ks++) {
            const int k0 = ks * 8;
            uint32_t a[4];
            const float* ap = Ps + (16 * w + g) * PSTR + k0 + t;
            a[0] = __float_as_uint(ap[0]);
            a[1] = __float_as_uint(ap[8 * PSTR]);
            a[2] = __float_as_uint(ap[4]);
            a[3] = __float_as_uint(ap[8 * PSTR + 4]);
            #pragma unroll
            for (int nf = 0; nf < 8; nf++) {
                uint32_t b[2];
                b[0] = __float_as_uint(Vs[(k0 + t) * VSTR + nf * 8 + g]);
                b[1] = __float_as_uint(Vs[(k0 + t + 4) * VSTR + nf * 8 + g]);
                mma_tf32(o[nf], a, b);
            }
        }

        // ---- pipeline turn: wait next K/V, prefetch sb+2, compute S(sb+1)
        //      (queued behind PV(sb) in the tensor pipe; next softmax's
        //       chain overlaps the drain) ----
        if (sb < sbmax) {
            CP_WAIT0();
            __syncthreads();   // all warps' V(sb)/K(sb) reads complete (pre-HMMA)
            if (sb + 2 <= sbmax) {
                attn_issue_kv(kp, vp, sb32, sb + 2, buf, tid);
                CP_COMMIT();
            }
            attn_s_mma(s, qf, sf + KS_OFF + (buf ^ 1) * KBUF, g, t);
        }
    }

    // ---- epilogue ----
    const int b = bh >> 4, h = bh & 15;
    const float invA = 1.0f / lA;
    const float invB = 1.0f / lB;
    float* dstA = g_att + ((size_t)(b * T_ + rowA)) * C_ + h * D_;
    float* dstB = g_att + ((size_t)(b * T_ + rowA + 8)) * C_ + h * D_;
    #pragma unroll
    for (int nf = 0; nf < 8; nf++) {
        const int cc = nf * 8 + 2 * t;
        *(float2*)(dstA + cc) =
            make_float2(to_tf32(o[nf][0] * invA), to_tf32(o[nf][1] * invA));
        *(float2*)(dstB + cc) =
            make_float2(to_tf32(o[nf][2] * invB), to_tf32(o[nf][3] * invB));
    }
}

// ===========================================================================
extern "C" void kernel_launch(void* const* d_in, const int* in_sizes, int n_in,
                              void* d_out, int out_size)
{
    const float* x  = (const float*)d_in[0];
    const float* Wq = (const float*)d_in[1];
    const float* Wk = (const float*)d_in[2];
    const float* Wv = (const float*)d_in[3];
    const float* Wo = (const float*)d_in[4];
    const float* bo = (const float*)d_in[5];
    float* out = (float*)d_out;

    cudaFuncSetAttribute(attn_mma_kernel, cudaFuncAttributeMaxDynamicSharedMemorySize,
                         ATTN_SMEM_BYTES);
    cudaFuncSetAttribute(qkv_tc, cudaFuncAttributeMaxDynamicSharedMemorySize,
                         GEMM_SMEM_BYTES);
    cudaFuncSetAttribute(proj_tc, cudaFuncAttributeMaxDynamicSharedMemorySize,
                         GEMM_SMEM_BYTES);

    round_x<<<BT_ * C_ / (256 * 4), 256>>>(x);
    transpose_qkv_w<<<dim3(32, 2, 48), 256>>>(Wq, Wk, Wv);
    transpose_wo<<<dim3(32, 32), 256>>>(Wo);
    qkv_tc<<<dim3(64, 24), 128, GEMM_SMEM_BYTES>>>();
    attn_mma_kernel<<<dim3(T_ / 128, B_ * H_), 256, ATTN_SMEM_BYTES>>>();
    proj_tc<<<dim3(64, 8), 128, GEMM_SMEM_BYTES>>>(out, bo);
}

// round 10
// speedup vs baseline: 1.9903x; 1.9254x over previous
#include <cuda_runtime.h>
#include <cuda_fp16.h>
#include <math.h>
#include <cstdint>

// Problem constants
#define B_ 4
#define T_ 2048
#define C_ 1024
#define H_ 16
#define D_ 64
#define BT_ (B_ * T_)           // 8192

// Scratch (fp16 end-to-end; fp32 only in accumulators and final out)
__device__ __half g_q[B_ * H_ * T_ * D_];    // [B,H,T,D], pre-scaled by 0.125
__device__ __half g_k[B_ * H_ * T_ * D_];    // [B,H,T,D]
__device__ __half g_vt[B_ * H_ * D_ * T_];   // [B,H,D,T]  (V transposed)
__device__ __half g_att[B_ * T_ * C_];       // [B,T,H*D]
__device__ __half g_wt[3 * C_ * C_];         // K-major qkv weights [n=3072][k=1024]
__device__ __half g_wot[C_ * C_];            // K-major Wo [n=1024][k=1024]
__device__ __half g_xh[BT_ * C_];            // fp16 x

// ===========================================================================
// Helpers
// ===========================================================================
__device__ __forceinline__ void mma_fp16(float* c, const uint32_t* a, const uint32_t* b) {
    asm volatile(
        "mma.sync.aligned.m16n8k16.row.col.f32.f16.f16.f32 "
        "{%0,%1,%2,%3}, {%4,%5,%6,%7}, {%8,%9}, {%0,%1,%2,%3};\n"
        : "+f"(c[0]), "+f"(c[1]), "+f"(c[2]), "+f"(c[3])
        : "r"(a[0]), "r"(a[1]), "r"(a[2]), "r"(a[3]),
          "r"(b[0]), "r"(b[1]));
}

__device__ __forceinline__ uint32_t smem_u32(const void* p) {
    return (uint32_t)__cvta_generic_to_shared(p);
}

__device__ __forceinline__ uint32_t pack_h2(float lo, float hi) {
    __half2 h = __halves2half2(__float2half_rn(lo), __float2half_rn(hi));
    return *reinterpret_cast<uint32_t*>(&h);
}

#define CPA16(dst, src) \
    asm volatile("cp.async.ca.shared.global [%0], [%1], 16;" :: "r"(dst), "l"(src))
#define CP_COMMIT() asm volatile("cp.async.commit_group;" ::: "memory")
#define CP_WAIT0()  asm volatile("cp.async.wait_group 0;" ::: "memory")

extern __shared__ __align__(16) __half dyn_smh[];

// ===========================================================================
// Dense GEMM (fp16): 128 threads / 4 warps, warp tile 64x64, block 128x128x64.
// 2-stage cp.async.  SMEM row stride 72 halves (36 words -> bank 4g+t, CF).
// ===========================================================================
#define HSTR 72
#define TILEH (128 * HSTR)                 // 9216 halves
#define BUFH  (2 * TILEH)                  // A+B per stage
#define GEMM_SMEM_BYTES (2 * BUFH * 2)     // 73728 bytes

__device__ __forceinline__ void gemm_issue_chunk(
    const __half* __restrict__ A0, const __half* __restrict__ B0,
    uint32_t sb32, int kc, int buf, int pr, int pc8)
{
    const uint32_t abase = sb32 + (uint32_t)(buf * BUFH) * 2;
    const uint32_t bbase = abase + (uint32_t)TILEH * 2;
    #pragma unroll
    for (int l = 0; l < 8; l++) {
        const int r = pr + l * 16;
        const uint32_t so = (uint32_t)(r * HSTR + pc8 * 8) * 2;
        CPA16(abase + so, A0 + (size_t)r * C_ + kc * 64 + pc8 * 8);
        CPA16(bbase + so, B0 + (size_t)r * C_ + kc * 64 + pc8 * 8);
    }
}

__device__ __forceinline__ void gemm_mainloop_fp16(
    const __half* __restrict__ A0, const __half* __restrict__ B0,
    float c[4][8][4])
{
    const int tid  = threadIdx.x;
    const int lane = tid & 31;
    const int wid  = tid >> 5;
    const int wm = (wid & 1) * 64;
    const int wn = (wid >> 1) * 64;
    const int g = lane >> 2;
    const int t = lane & 3;
    const int pc8 = tid & 7;
    const int pr  = tid >> 3;            // 0..15

    const uint32_t sb32 = smem_u32(dyn_smh);

    #pragma unroll
    for (int mf = 0; mf < 4; mf++)
        #pragma unroll
        for (int nf = 0; nf < 8; nf++)
            #pragma unroll
            for (int r = 0; r < 4; r++) c[mf][nf][r] = 0.0f;

    gemm_issue_chunk(A0, B0, sb32, 0, 0, pr, pc8);
    CP_COMMIT();

    for (int kc = 0; kc < 16; kc++) {
        const int buf = kc & 1;
        CP_WAIT0();
        __syncthreads();
        if (kc < 15) {
            gemm_issue_chunk(A0, B0, sb32, kc + 1, buf ^ 1, pr, pc8);
            CP_COMMIT();
        }

        const __half* sA = dyn_smh + buf * BUFH;
        const __half* sB = sA + TILEH;

        #pragma unroll
        for (int ks = 0; ks < 4; ks++) {
            const int k0 = ks * 16;
            uint32_t a[4][4];
            #pragma unroll
            for (int mf = 0; mf < 4; mf++) {
                const __half* ap = sA + (wm + mf * 16 + g) * HSTR + k0 + 2 * t;
                a[mf][0] = *(const uint32_t*)(ap);
                a[mf][1] = *(const uint32_t*)(ap + 8 * HSTR);
                a[mf][2] = *(const uint32_t*)(ap + 8);
                a[mf][3] = *(const uint32_t*)(ap + 8 * HSTR + 8);
            }
            uint32_t b[8][2];
            #pragma unroll
            for (int nf = 0; nf < 8; nf++) {
                const __half* bp = sB + (wn + nf * 8 + g) * HSTR + k0 + 2 * t;
                b[nf][0] = *(const uint32_t*)(bp);
                b[nf][1] = *(const uint32_t*)(bp + 8);
            }
            #pragma unroll
            for (int mf = 0; mf < 4; mf++)
                #pragma unroll
                for (int nf = 0; nf < 8; nf++)
                    mma_fp16(c[mf][nf], a[mf], b[nf]);
        }
    }
}

// ===========================================================================
// Producer-side conversion kernels
// ===========================================================================
__global__ __launch_bounds__(256) void convert_x(const float* __restrict__ x)
{
    const int base = (blockIdx.x * 256 + threadIdx.x) * 8;
    float4 v0 = *(const float4*)(x + base);
    float4 v1 = *(const float4*)(x + base + 4);
    uint4 o;
    o.x = pack_h2(v0.x, v0.y);
    o.y = pack_h2(v0.z, v0.w);
    o.z = pack_h2(v1.x, v1.y);
    o.w = pack_h2(v1.z, v1.w);
    *(uint4*)(g_xh + base) = o;
}

__global__ __launch_bounds__(256) void transpose_qkv_w(
    const float* __restrict__ Wq, const float* __restrict__ Wk,
    const float* __restrict__ Wv)
{
    __shared__ float tile[32][33];
    const int z = blockIdx.z;
    const int which = z >> 4, h = z & 15;
    const float* W = (which == 0 ? Wq : (which == 1 ? Wk : Wv)) + (size_t)h * C_ * D_;
    const int c0 = blockIdx.x * 32;
    const int d0 = blockIdx.y * 32;
    const int tx = threadIdx.x & 31, ty = threadIdx.x >> 5;

    #pragma unroll
    for (int i = 0; i < 4; i++)
        tile[ty + i * 8][tx] = W[(size_t)(c0 + ty + i * 8) * D_ + d0 + tx];
    __syncthreads();
    const int nbase = which * 1024 + h * 64 + d0;
    #pragma unroll
    for (int i = 0; i < 4; i++)
        g_wt[(size_t)(nbase + ty + i * 8) * C_ + c0 + tx] =
            __float2half_rn(tile[tx][ty + i * 8]);
}

__global__ __launch_bounds__(256) void transpose_wo(const float* __restrict__ Wo)
{
    __shared__ float tile[32][33];
    const int c0 = blockIdx.x * 32;
    const int n0 = blockIdx.y * 32;
    const int tx = threadIdx.x & 31, ty = threadIdx.x >> 5;
    #pragma unroll
    for (int i = 0; i < 4; i++)
        tile[ty + i * 8][tx] = Wo[(size_t)(c0 + ty + i * 8) * C_ + n0 + tx];
    __syncthreads();
    #pragma unroll
    for (int i = 0; i < 4; i++)
        g_wot[(size_t)(n0 + ty + i * 8) * C_ + c0 + tx] =
            __float2half_rn(tile[tx][ty + i * 8]);
}

// ===========================================================================
// Kernel 1: QKV projection (fp16).  grid (64, 24), 128 threads.
// q pre-scaled by 0.125; v written transposed to g_vt[B,H,D,T].
// ===========================================================================
__global__ __launch_bounds__(128, 2) void qkv_tc()
{
    const int mt = blockIdx.x, nt = blockIdx.y;
    const __half* A0 = g_xh + (size_t)mt * 128 * C_;
    const __half* B0 = g_wt + (size_t)nt * 128 * C_;

    float c[4][8][4];
    gemm_mainloop_fp16(A0, B0, c);

    const int tid  = threadIdx.x;
    const int lane = tid & 31;
    const int wid  = tid >> 5;
    const int wm = (wid & 1) * 64;
    const int wn = (wid >> 1) * 64;
    const int g = lane >> 2;
    const int t4 = lane & 3;

    const int nb0 = nt * 128 + wn;
    const int which = nb0 >> 10;
    const int hh = (nb0 >> 6) & 15;

    if (which == 2) {
        // V: write transposed [B,H,D,T] as u16 scatters
        #pragma unroll
        for (int mf = 0; mf < 4; mf++) {
            #pragma unroll
            for (int half = 0; half < 2; half++) {
                const int m = mt * 128 + wm + mf * 16 + g + half * 8;
                const int b = m >> 11, tt = m & (T_ - 1);
                __half* vb = g_vt + ((size_t)(b * H_ + hh) * D_) * T_;
                #pragma unroll
                for (int nf = 0; nf < 8; nf++) {
                    const int d = nf * 8 + t4 * 2;
                    const float cv0 = c[mf][nf][half * 2 + 0];
                    const float cv1 = c[mf][nf][half * 2 + 1];
                    vb[(size_t)d * T_ + tt]       = __float2half_rn(cv0);
                    vb[(size_t)(d + 1) * T_ + tt] = __float2half_rn(cv1);
                }
            }
        }
    } else {
        const float sc = (which == 0) ? 0.125f : 1.0f;
        __half* outb = (which == 0 ? g_q : g_k);
        #pragma unroll
        for (int mf = 0; mf < 4; mf++) {
            #pragma unroll
            for (int half = 0; half < 2; half++) {
                const int m = mt * 128 + wm + mf * 16 + g + half * 8;
                const int b = m >> 11, tt = m & (T_ - 1);
                __half* op = outb + ((size_t)(b * H_ + hh) * T_ + tt) * D_;
                #pragma unroll
                for (int nf = 0; nf < 8; nf++) {
                    const int d = nf * 8 + t4 * 2;
                    *(uint32_t*)(op + d) = pack_h2(c[mf][nf][half * 2] * sc,
                                                   c[mf][nf][half * 2 + 1] * sc);
                }
            }
        }
    }
}

// ===========================================================================
// Kernel 3: output projection + bias (fp16 in, fp32 out).  grid (64, 8).
// ===========================================================================
__global__ __launch_bounds__(128, 2) void proj_tc(float* __restrict__ out,
                                                  const float* __restrict__ bo)
{
    const int mt = blockIdx.x, nt = blockIdx.y;
    const __half* A0 = g_att + (size_t)mt * 128 * C_;
    const __half* B0 = g_wot + (size_t)nt * 128 * C_;

    float c[4][8][4];
    gemm_mainloop_fp16(A0, B0, c);

    const int tid  = threadIdx.x;
    const int lane = tid & 31;
    const int wid  = tid >> 5;
    const int wm = (wid & 1) * 64;
    const int wn = (wid >> 1) * 64;
    const int g = lane >> 2;
    const int t4 = lane & 3;

    #pragma unroll
    for (int mf = 0; mf < 4; mf++) {
        #pragma unroll
        for (int half = 0; half < 2; half++) {
            const int m = mt * 128 + wm + mf * 16 + g + half * 8;
            #pragma unroll
            for (int nf = 0; nf < 8; nf++) {
                const int n = nt * 128 + wn + nf * 8 + t4 * 2;
                float2 bv = *(const float2*)(bo + n);
                float2 v = make_float2(c[mf][nf][half * 2] + bv.x,
                                       c[mf][nf][half * 2 + 1] + bv.y);
                *(float2*)(out + (size_t)m * C_ + n) = v;
            }
        }
    }
}

// ===========================================================================
// Kernel 2: fp16 tensor-core causal flash attention.
// BQ=128, BS=64, 256 threads.  Q/P share one SMEM region (warp-private rows).
// All SMEM rows stride 72 halves -> conflict-free fragments.
// ===========================================================================
#define AQP 0                        // Q then P: 128 x 72 halves
#define AKS (128 * HSTR)             // 9216
#define AKB (64 * HSTR)              // 4608
#define AVS (AKS + 2 * AKB)          // 18432
#define AVB (64 * HSTR)
#define ATTN_SMEM_BYTES ((AVS + 2 * AVB) * 2)   // 55296 bytes

__device__ __forceinline__ void attn_issue_kv(
    const __half* __restrict__ kp, const __half* __restrict__ vtp,
    uint32_t sb32, int sb, int buf, int tid)
{
    const uint32_t kdst = sb32 + (uint32_t)(AKS + buf * AKB) * 2;
    const uint32_t vdst = sb32 + (uint32_t)(AVS + buf * AVB) * 2;
    #pragma unroll
    for (int l = 0; l < 2; l++) {
        const int idx = tid + l * 256;   // 0..511
        const int r = idx >> 3, c8 = idx & 7;
        CPA16(kdst + (uint32_t)(r * HSTR + c8 * 8) * 2,
              kp + (size_t)(sb * 64 + r) * D_ + c8 * 8);
        CPA16(vdst + (uint32_t)(r * HSTR + c8 * 8) * 2,
              vtp + (size_t)r * T_ + sb * 64 + c8 * 8);
    }
}

__global__ __launch_bounds__(256, 2) void attn_mma_kernel()
{
    __half* sfh = dyn_smh;
    const int tid  = threadIdx.x;
    const int lane = tid & 31;
    const int w    = tid >> 5;
    const int g    = lane >> 2;
    const int t    = lane & 3;
    const int qb   = blockIdx.x;        // 0..15
    const int bh   = blockIdx.y;        // 0..63

    const __half* qp  = g_q  + (size_t)bh * T_ * D_;
    const __half* kp  = g_k  + (size_t)bh * T_ * D_;
    const __half* vtp = g_vt + (size_t)bh * D_ * T_;
    const uint32_t sb32 = smem_u32(sfh);

    // stage Q (already 0.125-scaled) + K/V(0) via cp.async
    attn_issue_kv(kp, vtp, sb32, 0, 0, tid);
    #pragma unroll
    for (int l = 0; l < 4; l++) {
        const int idx = tid + l * 256;   // 0..1023
        const int r = idx >> 3, c8 = idx & 7;
        CPA16(sb32 + (uint32_t)(AQP + r * HSTR + c8 * 8) * 2,
              qp + (size_t)(qb * 128 + r) * D_ + c8 * 8);
    }
    CP_COMMIT();
    CP_WAIT0();
    __syncthreads();

    // extract Q fragments (own warp rows only)
    uint32_t qf[4][4];
    #pragma unroll
    for (int ks = 0; ks < 4; ks++) {
        const __half* ap = sfh + AQP + (16 * w + g) * HSTR + ks * 16 + 2 * t;
        qf[ks][0] = *(const uint32_t*)(ap);
        qf[ks][1] = *(const uint32_t*)(ap + 8 * HSTR);
        qf[ks][2] = *(const uint32_t*)(ap + 8);
        qf[ks][3] = *(const uint32_t*)(ap + 8 * HSTR + 8);
    }

    float o[8][4];
    #pragma unroll
    for (int nf = 0; nf < 8; nf++)
        #pragma unroll
        for (int r = 0; r < 4; r++) o[nf][r] = 0.0f;

    float mA = -1e30f, mB = -1e30f, lA = 0.0f, lB = 0.0f;
    const int rowA = qb * 128 + 16 * w + g;
    const int sbmax = qb * 2 + 1;

    // prefetch K/V(1)
    attn_issue_kv(kp, vtp, sb32, 1, 1, tid);
    CP_COMMIT();

    for (int sb = 0; sb <= sbmax; sb++) {
        const int buf = sb & 1;
        if (sb > 0) {
            CP_WAIT0();
            __syncthreads();
            if (sb + 1 <= sbmax) {
                attn_issue_kv(kp, vtp, sb32, sb + 1, buf ^ 1, tid);
                CP_COMMIT();
            }
        }
        const __half* Ks = sfh + AKS + buf * AKB;
        const __half* Vs = sfh + AVS + buf * AVB;

        // ---- S = Q @ K^T ----
        float s[8][4];
        #pragma unroll
        for (int nf = 0; nf < 8; nf++)
            #pragma unroll
            for (int r = 0; r < 4; r++) s[nf][r] = 0.0f;

        #pragma unroll
        for (int ks = 0; ks < 4; ks++) {
            const int k0 = ks * 16;
            #pragma unroll
            for (int nf = 0; nf < 8; nf++) {
                uint32_t b[2];
                const __half* bp = Ks + (nf * 8 + g) * HSTR + k0 + 2 * t;
                b[0] = *(const uint32_t*)(bp);
                b[1] = *(const uint32_t*)(bp + 8);
                mma_fp16(s[nf], qf[ks], b);
            }
        }

        // ---- causal mask ----
        if (sb * 64 + 63 > qb * 128 + 16 * w) {
            #pragma unroll
            for (int nf = 0; nf < 8; nf++) {
                const int c0 = sb * 64 + nf * 8 + 2 * t;
                if (c0 > rowA)     s[nf][0] = -1e30f;
                if (c0 + 1 > rowA) s[nf][1] = -1e30f;
                if (c0 > rowA + 8)     s[nf][2] = -1e30f;
                if (c0 + 1 > rowA + 8) s[nf][3] = -1e30f;
            }
        }

        // ---- online softmax (fp32) ----
        float mxA = -1e30f, mxB = -1e30f;
        #pragma unroll
        for (int nf = 0; nf < 8; nf++) {
            mxA = fmaxf(mxA, fmaxf(s[nf][0], s[nf][1]));
            mxB = fmaxf(mxB, fmaxf(s[nf][2], s[nf][3]));
        }
        mxA = fmaxf(mxA, __shfl_xor_sync(0xFFFFFFFF, mxA, 1));
        mxA = fmaxf(mxA, __shfl_xor_sync(0xFFFFFFFF, mxA, 2));
        mxB = fmaxf(mxB, __shfl_xor_sync(0xFFFFFFFF, mxB, 1));
        mxB = fmaxf(mxB, __shfl_xor_sync(0xFFFFFFFF, mxB, 2));

        const float mnA = fmaxf(mA, mxA);
        const float mnB = fmaxf(mB, mxB);
        const float aA = __expf(mA - mnA);
        const float aB = __expf(mB - mnB);
        mA = mnA; mB = mnB;

        float suA = 0.0f, suB = 0.0f;
        uint32_t p0h[8], p1h[8];
        #pragma unroll
        for (int nf = 0; nf < 8; nf++) {
            float p0 = __expf(s[nf][0] - mnA);
            float p1 = __expf(s[nf][1] - mnA);
            float p2 = __expf(s[nf][2] - mnB);
            float p3 = __expf(s[nf][3] - mnB);
            suA += p0 + p1; suB += p2 + p3;
            p0h[nf] = pack_h2(p0, p1);
            p1h[nf] = pack_h2(p2, p3);
        }
        suA += __shfl_xor_sync(0xFFFFFFFF, suA, 1);
        suA += __shfl_xor_sync(0xFFFFFFFF, suA, 2);
        suB += __shfl_xor_sync(0xFFFFFFFF, suB, 1);
        suB += __shfl_xor_sync(0xFFFFFFFF, suB, 2);
        lA = lA * aA + suA;
        lB = lB * aB + suB;

        #pragma unroll
        for (int nf = 0; nf < 8; nf++) {
            o[nf][0] *= aA; o[nf][1] *= aA;
            o[nf][2] *= aB; o[nf][3] *= aB;
        }

        // ---- P (fp16) to warp-private SMEM rows (Q region reuse) ----
        #pragma unroll
        for (int nf = 0; nf < 8; nf++) {
            *(uint32_t*)(sfh + AQP + (16 * w + g) * HSTR + nf * 8 + 2 * t) = p0h[nf];
            *(uint32_t*)(sfh + AQP + (16 * w + g + 8) * HSTR + nf * 8 + 2 * t) = p1h[nf];
        }
        __syncwarp();

        // ---- O += P @ V ----
        #pragma unroll
        for (int ks = 0; ks < 4; ks++) {
            const int k0 = ks * 16;
            uint32_t a[4];
            const __half* ap = sfh + AQP + (16 * w + g) * HSTR + k0 + 2 * t;
            a[0] = *(const uint32_t*)(ap);
            a[1] = *(const uint32_t*)(ap + 8 * HSTR);
            a[2] = *(const uint32_t*)(ap + 8);
            a[3] = *(const uint32_t*)(ap + 8 * HSTR + 8);
            #pragma unroll
            for (int nf = 0; nf < 8; nf++) {
                uint32_t b[2];
                const __half* bp = Vs + (nf * 8 + g) * HSTR + k0 + 2 * t;
                b[0] = *(const uint32_t*)(bp);
                b[1] = *(const uint32_t*)(bp + 8);
                mma_fp16(o[nf], a, b);
            }
        }
        __syncwarp();   // P reads done before next iteration's P writes
    }

    // ---- epilogue: normalize, fp16 to g_att ----
    const int b = bh >> 4, h = bh & 15;
    const float invA = 1.0f / lA;
    const float invB = 1.0f / lB;
    __half* dstA = g_att + ((size_t)(b * T_ + rowA)) * C_ + h * D_;
    __half* dstB = g_att + ((size_t)(b * T_ + rowA + 8)) * C_ + h * D_;
    #pragma unroll
    for (int nf = 0; nf < 8; nf++) {
        const int cc = nf * 8 + 2 * t;
        *(uint32_t*)(dstA + cc) = pack_h2(o[nf][0] * invA, o[nf][1] * invA);
        *(uint32_t*)(dstB + cc) = pack_h2(o[nf][2] * invB, o[nf][3] * invB);
    }
}

// ===========================================================================
extern "C" void kernel_launch(void* const* d_in, const int* in_sizes, int n_in,
                              void* d_out, int out_size)
{
    const float* x  = (const float*)d_in[0];
    const float* Wq = (const float*)d_in[1];
    const float* Wk = (const float*)d_in[2];
    const float* Wv = (const float*)d_in[3];
    const float* Wo = (const float*)d_in[4];
    const float* bo = (const float*)d_in[5];
    float* out = (float*)d_out;

    cudaFuncSetAttribute(attn_mma_kernel, cudaFuncAttributeMaxDynamicSharedMemorySize,
                         ATTN_SMEM_BYTES);
    cudaFuncSetAttribute(qkv_tc, cudaFuncAttributeMaxDynamicSharedMemorySize,
                         GEMM_SMEM_BYTES);
    cudaFuncSetAttribute(proj_tc, cudaFuncAttributeMaxDynamicSharedMemorySize,
                         GEMM_SMEM_BYTES);

    convert_x<<<BT_ * C_ / (256 * 8), 256>>>(x);
    transpose_qkv_w<<<dim3(32, 2, 48), 256>>>(Wq, Wk, Wv);
    transpose_wo<<<dim3(32, 32), 256>>>(Wo);
    qkv_tc<<<dim3(64, 24), 128, GEMM_SMEM_BYTES>>>();
    attn_mma_kernel<<<dim3(T_ / 128, B_ * H_), 256, ATTN_SMEM_BYTES>>>();
    proj_tc<<<dim3(64, 8), 128, GEMM_SMEM_BYTES>>>(out, bo);
}